// round 16
// baseline (speedup 1.0000x reference)
#include <cuda_runtime.h>
#include <cuda_bf16.h>
#include <cstdint>

#define NG      40
#define CPG     8
#define CCH     12
#define BB      4
#define HH_     64
#define WW_     128
#define DD_     48
#define HW      (HH_*WW_)         /* 8192 */
#define DHW     ((size_t)DD_*HW)  /* 393216 */

// Scratch (device globals — no allocation APIs)
__device__ float g_vol[(size_t)BB*64*DD_*HH_*WW_];
__device__ float g_x1 [(size_t)BB*32*DD_*HH_*WW_];
// B fragments: [tap 27][ks 4][nt 4][lane 32] uint4 = {bh0,bh1,bl0,bl1}
__device__ uint4 g_bf1[27*16*32];
__device__ uint4 g_bf2[27*16*32];

__device__ __forceinline__ uint32_t smem_u32(const void* p) {
    uint32_t a;
    asm("{ .reg .u64 t; cvta.to.shared.u64 t, %1; cvt.u32.u64 %0, t; }" : "=r"(a) : "l"(p));
    return a;
}

#define MMA16816(c0,c1,c2,c3, a0,a1,a2,a3, b0,b1) \
    asm volatile("mma.sync.aligned.m16n8k16.row.col.f32.bf16.bf16.f32 " \
        "{%0,%1,%2,%3}, {%4,%5,%6,%7}, {%8,%9}, {%0,%1,%2,%3};" \
        : "+f"(c0),"+f"(c1),"+f"(c2),"+f"(c3) \
        : "r"(a0),"r"(a1),"r"(a2),"r"(a3),"r"(b0),"r"(b1))

#define LDSM4(r0,r1,r2,r3, a) \
    asm volatile("ldmatrix.sync.aligned.m8n8.x4.shared.b16 {%0,%1,%2,%3}, [%4];" \
        : "=r"(r0),"=r"(r1),"=r"(r2),"=r"(r3) : "r"(a))

// ---------------------------------------------------------------------------
// Kernel 1: build cost volume (unchanged — 148us, HBM-bound)
// ---------------------------------------------------------------------------
__global__ __launch_bounds__(256)
void build_volume_kernel(const float* __restrict__ lg,
                         const float* __restrict__ rg,
                         const float* __restrict__ lc,
                         const float* __restrict__ rc)
{
    __shared__ float lgs[32][WW_];
    __shared__ float rgs[32][WW_];

    const int b     = blockIdx.x / HH_;
    const int h     = blockIdx.x % HH_;
    const int chunk = blockIdx.y;
    const int tid   = threadIdx.x;
    const int w     = tid & 127;
    const int t2    = tid >> 7;

    if (chunk < 10) {
        for (int i = tid; i < 32 * WW_; i += 256) {
            int ch = i >> 7, ww = i & 127;
            int cg = chunk * 32 + ch;
            lgs[ch][ww] = lg[((size_t)(b * 320 + cg) * HH_ + h) * WW_ + ww];
            rgs[ch][ww] = rg[((size_t)(b * 320 + cg) * HH_ + h) * WW_ + ww];
        }
        __syncthreads();
        for (int gi = 0; gi < 2; ++gi) {
            int g = t2 + gi * 2;
            float lreg[CPG];
            #pragma unroll
            for (int c = 0; c < CPG; ++c) lreg[c] = lgs[g * CPG + c][w];
            int gout = chunk * 4 + g;
            float* outp = g_vol + (size_t)(b * 64 + gout) * DHW + (size_t)h * WW_ + w;
            #pragma unroll 4
            for (int d = 0; d < DD_; ++d) {
                float v = 0.f;
                if (w >= d) {
                    float s = 0.f;
                    #pragma unroll
                    for (int c = 0; c < CPG; ++c)
                        s += lreg[c] * rgs[g * CPG + c][w - d];
                    v = s * (1.0f / CPG);
                }
                outp[(size_t)d * HW] = v;
            }
        }
    } else {
        for (int i = tid; i < 24 * WW_; i += 256) {
            int ch = i >> 7, ww = i & 127;
            lgs[ch][ww] = (ch < 12)
                ? lc[((size_t)(b * CCH + ch)      * HH_ + h) * WW_ + ww]
                : rc[((size_t)(b * CCH + (ch-12)) * HH_ + h) * WW_ + ww];
        }
        __syncthreads();
        for (int idx = t2; idx < 24 * DD_; idx += 2) {
            int ch = idx / DD_, d = idx % DD_;
            float v = 0.f;
            if (w >= d) v = (ch < 12) ? lgs[ch][w] : lgs[ch][w - d];
            g_vol[(size_t)(b * 64 + 40 + ch) * DHW + (size_t)d * HW + (size_t)h * WW_ + w] = v;
        }
    }
}

// ---------------------------------------------------------------------------
// Kernel 1b: prepack weights into per-lane mma B fragments (uint4: hi|lo).
// ---------------------------------------------------------------------------
__global__ void prepack_w(const float* __restrict__ w1, const float* __restrict__ w2)
{
    const int tap = blockIdx.x;   // 0..26
    for (int e = threadIdx.x; e < 512; e += 256) {
        const int ks   = e >> 7;
        const int nt   = (e >> 5) & 3;
        const int lane = e & 31;
        const int t4 = lane & 3, gg = lane >> 2;
        const int co = nt * 8 + gg;
        const int k0 = ks * 16 + t4 * 2;
        const int kk[4] = {k0, k0 + 1, k0 + 8, k0 + 9};
        const size_t idx = ((size_t)tap * 16 + ks * 4 + nt) * 32 + lane;
        {
            uint16_t uh[4], ul[4];
            #pragma unroll
            for (int i = 0; i < 4; ++i) {
                float f = w1[((size_t)co * 64 + kk[i]) * 27 + tap];
                __nv_bfloat16 hi = __float2bfloat16(f);
                uh[i] = __bfloat16_as_ushort(hi);
                ul[i] = __bfloat16_as_ushort(__float2bfloat16(f - __bfloat162float(hi)));
            }
            uint4 r;
            r.x = ((uint32_t)uh[1] << 16) | uh[0];
            r.y = ((uint32_t)uh[3] << 16) | uh[2];
            r.z = ((uint32_t)ul[1] << 16) | ul[0];
            r.w = ((uint32_t)ul[3] << 16) | ul[2];
            g_bf1[idx] = r;
        }
        {
            uint16_t uh[4], ul[4];
            #pragma unroll
            for (int i = 0; i < 4; ++i) {
                float f = (kk[i] < 32) ? w2[((size_t)co * 32 + kk[i]) * 27 + tap] : 0.f;
                __nv_bfloat16 hi = __float2bfloat16(f);
                uh[i] = __bfloat16_as_ushort(hi);
                ul[i] = __bfloat16_as_ushort(__float2bfloat16(f - __bfloat162float(hi)));
            }
            uint4 r;
            r.x = ((uint32_t)uh[1] << 16) | uh[0];
            r.y = ((uint32_t)uh[3] << 16) | uh[2];
            r.z = ((uint32_t)ul[1] << 16) | ul[0];
            r.w = ((uint32_t)ul[3] << 16) | ul[2];
            g_bf2[idx] = r;
        }
    }
}

// ---------------------------------------------------------------------------
// Kernel 2/3: conv3d 3x3x3 + BN + ReLU via mma.sync bf16 hi/lo 3-pass.
//   TH=2: CTA = (b, d, h-pair). 256 threads = 2 warpgroups of 4 warps.
//   Stage = (kd, ihh 0..3): fill ONE plane (id, ih=2h0-1+ihh); wg g computes
//   tap (kd, kh=ihh-g) for output h=2h0+g when 0<=kh<=2.
//   Per output row: 6 fills / 6 sync-pairs instead of 9 (planes shared).
// ---------------------------------------------------------------------------
template<int CI, int KSTEPS, int ROWB>
__global__ __launch_bounds__(256, 3)
void conv_mma(const float* __restrict__ in, const uint4* __restrict__ bfrag,
              const float* __restrict__ gamma, const float* __restrict__ beta,
              const float* __restrict__ mean, const float* __restrict__ var,
              float* __restrict__ out, int bz)
{
    constexpr int CIH = CI / 2;        // ci per fill-half
    __shared__ __align__(16) uint8_t smA[2][130 * ROWB];
    __shared__ float2 s_bn[32];

    const int h0 = blockIdx.x;                    // h-pair index (0..31)
    const int d = blockIdx.y, b = blockIdx.z + bz;
    const int tid = threadIdx.x, wid = tid >> 5, lane = tid & 31;
    const int wg = wid >> 2, wr = wid & 3;        // warpgroup, warp-in-group
    const int g = lane >> 2, t4 = lane & 3;
    const int h_out = 2 * h0 + wg;

    // zero edge rows (w=-1 -> row 0, w=128 -> row 129) in both buffers
    for (int i = tid; i < 4 * (ROWB / 4); i += 256) {
        const int nw = ROWB / 4;
        int r = i / nw, wd = i % nw;
        int buf = r >> 1, row = (r & 1) ? 129 : 0;
        *(uint32_t*)&smA[buf][row * ROWB + wd * 4] = 0u;
    }
    if (tid < 32) {
        float iv = gamma[tid] * rsqrtf(var[tid] + 1e-5f);
        s_bn[tid] = make_float2(iv, beta[tid] - mean[tid] * iv);
    }
    __syncthreads();

    // ldmatrix x4 per-lane offset (within warpgroup M-tile)
    const int lj = lane >> 3, lr = lane & 7;
    const uint32_t aoff0 = (uint32_t)((wr * 32 + (lj & 1) * 8 + lr) * ROWB + (lj >> 1) * 16);
    const uint32_t baseHi = smem_u32(&smA[0][0]);
    const uint32_t baseLo = smem_u32(&smA[1][0]);

    float acc[2][4][4];    // [m-frag][ntile][4]
    #pragma unroll
    for (int mf = 0; mf < 2; ++mf)
        #pragma unroll
        for (int nt = 0; nt < 4; ++nt)
            #pragma unroll
            for (int i = 0; i < 4; ++i) acc[mf][nt][i] = 0.f;

    // fill assignment: thread owns one w column, one ci-half
    const int wcol = tid & 127;
    const int half = tid >> 7;
    const uint32_t rowbase = (uint32_t)((wcol + 1) * ROWB + half * CIH * 2);

    for (int kd = 0; kd < 3; ++kd) {
        const int id = d + kd - 1;
        if (id < 0 || id >= DD_) continue;
        for (int ihh = 0; ihh < 4; ++ihh) {
            const int ih = 2 * h0 - 1 + ihh;
            if (ih < 0 || ih >= HH_) continue;

            // ---- load + convert one plane half per thread ----
            uint2 pH[CIH / 4], pL[CIH / 4];
            {
                const float* pin = in + ((size_t)(b * CI + half * CIH) * DD_ + id)
                                        * ((size_t)HH_ * WW_) + (size_t)ih * WW_ + wcol;
                float fv[CIH];
                #pragma unroll
                for (int c = 0; c < CIH; ++c) fv[c] = pin[(size_t)c * DHW];
                #pragma unroll
                for (int q = 0; q < CIH / 4; ++q) {
                    uint16_t uh[4], ul[4];
                    #pragma unroll
                    for (int i = 0; i < 4; ++i) {
                        float f = fv[q * 4 + i];
                        __nv_bfloat16 hi = __float2bfloat16(f);
                        uh[i] = __bfloat16_as_ushort(hi);
                        ul[i] = __bfloat16_as_ushort(__float2bfloat16(f - __bfloat162float(hi)));
                    }
                    pH[q].x = ((uint32_t)uh[1] << 16) | uh[0];
                    pH[q].y = ((uint32_t)uh[3] << 16) | uh[2];
                    pL[q].x = ((uint32_t)ul[1] << 16) | ul[0];
                    pL[q].y = ((uint32_t)ul[3] << 16) | ul[2];
                }
            }
            __syncthreads();   // prior stage's mma reads done before overwrite
            #pragma unroll
            for (int q = 0; q < CIH / 4; ++q) {
                *(uint2*)&smA[0][rowbase + 8 * q] = pH[q];
                *(uint2*)&smA[1][rowbase + 8 * q] = pL[q];
            }
            __syncthreads();

            // ---- compute: this wg's tap (kd, kh) if valid ----
            const int kh = ihh - wg;
            if (kh >= 0 && kh <= 2) {
                #pragma unroll
                for (int kw = 0; kw < 3; ++kw) {
                    const int tap = kd * 9 + kh * 3 + kw;
                    const uint4* bp = bfrag + (size_t)tap * 512 + lane;
                    #pragma unroll
                    for (int ks = 0; ks < KSTEPS; ++ks) {
                        uint4 Bv[4];
                        #pragma unroll
                        for (int nt = 0; nt < 4; ++nt)
                            Bv[nt] = bp[(ks * 4 + nt) * 32];
                        const uint32_t ad = aoff0 + (uint32_t)(kw * ROWB + ks * 32);
                        #pragma unroll
                        for (int mf = 0; mf < 2; ++mf) {
                            const uint32_t adm = ad + (uint32_t)(mf * 16 * ROWB);
                            uint32_t ah0, ah1, ah2, ah3, al0, al1, al2, al3;
                            LDSM4(ah0, ah1, ah2, ah3, baseHi + adm);
                            LDSM4(al0, al1, al2, al3, baseLo + adm);
                            #pragma unroll
                            for (int nt = 0; nt < 4; ++nt) {
                                MMA16816(acc[mf][nt][0], acc[mf][nt][1], acc[mf][nt][2], acc[mf][nt][3],
                                         ah0, ah1, ah2, ah3, Bv[nt].x, Bv[nt].y);
                                MMA16816(acc[mf][nt][0], acc[mf][nt][1], acc[mf][nt][2], acc[mf][nt][3],
                                         ah0, ah1, ah2, ah3, Bv[nt].z, Bv[nt].w);
                                MMA16816(acc[mf][nt][0], acc[mf][nt][1], acc[mf][nt][2], acc[mf][nt][3],
                                         al0, al1, al2, al3, Bv[nt].x, Bv[nt].y);
                            }
                        }
                    }
                }
            }
        }
    }

    // ---- epilogue: BN + ReLU, direct STG ----
    float* ob = out + (size_t)(b * 32) * DHW + (size_t)d * HW + (size_t)h_out * WW_;
    #pragma unroll
    for (int mf = 0; mf < 2; ++mf) {
        const int wm = wr * 32 + mf * 16 + g;
        #pragma unroll
        for (int nt = 0; nt < 4; ++nt) {
            const int co = nt * 8 + t4 * 2;
            float2 bn0 = s_bn[co], bn1 = s_bn[co + 1];
            ob[(size_t)co * DHW + wm]           = fmaxf(acc[mf][nt][0] * bn0.x + bn0.y, 0.f);
            ob[(size_t)(co + 1) * DHW + wm]     = fmaxf(acc[mf][nt][1] * bn1.x + bn1.y, 0.f);
            ob[(size_t)co * DHW + wm + 8]       = fmaxf(acc[mf][nt][2] * bn0.x + bn0.y, 0.f);
            ob[(size_t)(co + 1) * DHW + wm + 8] = fmaxf(acc[mf][nt][3] * bn1.x + bn1.y, 0.f);
        }
    }
}

// ---------------------------------------------------------------------------

extern "C" void kernel_launch(void* const* d_in, const int* in_sizes, int n_in,
                              void* d_out, int out_size)
{
    const float* lg = (const float*)d_in[0];
    const float* rg = (const float*)d_in[1];
    const float* lc = (const float*)d_in[2];
    const float* rc = (const float*)d_in[3];
    const float* w1 = (const float*)d_in[4];
    const float* g1 = (const float*)d_in[5];
    const float* b1 = (const float*)d_in[6];
    const float* m1 = (const float*)d_in[7];
    const float* v1 = (const float*)d_in[8];
    const float* w2 = (const float*)d_in[9];
    const float* g2 = (const float*)d_in[10];
    const float* b2 = (const float*)d_in[11];
    const float* m2 = (const float*)d_in[12];
    const float* v2 = (const float*)d_in[13];
    float* out = (float*)d_out;

    float* vol = nullptr; float* x1 = nullptr;
    uint4* bf1 = nullptr; uint4* bf2 = nullptr;
    cudaGetSymbolAddress((void**)&vol, g_vol);
    cudaGetSymbolAddress((void**)&x1,  g_x1);
    cudaGetSymbolAddress((void**)&bf1, g_bf1);
    cudaGetSymbolAddress((void**)&bf2, g_bf2);

    // 1) cost volume
    dim3 gv(BB * HH_, 11);
    build_volume_kernel<<<gv, 256>>>(lg, rg, lc, rc);

    // 1b) weight prepack into mma fragments
    prepack_w<<<27, 256>>>(w1, w2);

    // 2) conv1 (64->32), split by batch so ncu's skip-5 capture lands on it
    dim3 gc(HH_ / 2, DD_, 1);
    conv_mma<64, 4, 144><<<gc, 256>>>(vol, bf1, g1, b1, m1, v1, x1, 0);
    conv_mma<64, 4, 144><<<gc, 256>>>(vol, bf1, g1, b1, m1, v1, x1, 1);
    conv_mma<64, 4, 144><<<gc, 256>>>(vol, bf1, g1, b1, m1, v1, x1, 2);
    conv_mma<64, 4, 144><<<gc, 256>>>(vol, bf1, g1, b1, m1, v1, x1, 3);

    // 3) conv2 (32->32)
    dim3 gc2(HH_ / 2, DD_, BB);
    conv_mma<32, 2, 80><<<gc2, 256>>>(x1, bf2, g2, b2, m2, v2, out, 0);
}